// round 1
// baseline (speedup 1.0000x reference)
#include <cuda_runtime.h>
#include <cuda_bf16.h>

// Problem constants (shapes fixed by setup_inputs)
#define FH 200
#define FW 304
#define FHW (FH * FW)
#define CPL 256        // channels per level
#define CTOT 768
#define NBOX 256
#define OH 7
#define OW 7
#define H1 100
#define W1 152
#define H2 50
#define W2 76

// Scratch: upsampled level-1 and level-2 feature maps at [256, 200, 304]
__device__ float g_up1[CPL * FHW];
__device__ float g_up2[CPL * FHW];

// ---------------------------------------------------------------------------
// Kernel 1: bilinear upsample (half-pixel, edge clamp == jax.image.resize
// 'bilinear' for these shapes) of feat1 (x2) and feat2 (x4) to 200x304.
// ---------------------------------------------------------------------------
__global__ void __launch_bounds__(256)
upsample_kernel(const float* __restrict__ feat1, const float* __restrict__ feat2) {
    int idx = blockIdx.x * blockDim.x + threadIdx.x;
    const int per_level = CPL * FHW;
    if (idx >= 2 * per_level) return;

    int lvl = idx >= per_level;
    int rem = idx - lvl * per_level;
    int c = rem / FHW;
    int p = rem - c * FHW;
    int Y = p / FW;
    int X = p - Y * FW;

    const float* src;
    float* dst;
    int Hs, Ws;
    float inv;
    if (lvl == 0) { src = feat1 + c * (H1 * W1); dst = g_up1; Hs = H1; Ws = W1; inv = 0.5f; }
    else          { src = feat2 + c * (H2 * W2); dst = g_up2; Hs = H2; Ws = W2; inv = 0.25f; }

    float fy = (Y + 0.5f) * inv - 0.5f;
    float fx = (X + 0.5f) * inv - 0.5f;
    fy = fminf(fmaxf(fy, 0.0f), (float)(Hs - 1));
    fx = fminf(fmaxf(fx, 0.0f), (float)(Ws - 1));
    int y0 = (int)fy;
    int x0 = (int)fx;
    int y1 = min(y0 + 1, Hs - 1);
    int x1 = min(x0 + 1, Ws - 1);
    float ly = fy - (float)y0;
    float lx = fx - (float)x0;
    float hy = 1.0f - ly;
    float hx = 1.0f - lx;

    const float* r0 = src + y0 * Ws;
    const float* r1 = src + y1 * Ws;
    float v = hy * (hx * __ldg(&r0[x0]) + lx * __ldg(&r0[x1]))
            + ly * (hx * __ldg(&r1[x0]) + lx * __ldg(&r1[x1]));
    dst[c * FHW + p] = v;
}

// ---------------------------------------------------------------------------
// Kernel 2: RoIAlign over the 3 (virtual) fused planes.
// One thread per output element; ow fastest for x-locality.
// ---------------------------------------------------------------------------
__global__ void __launch_bounds__(256)
roialign_kernel(const float* __restrict__ feat0,
                const float* __restrict__ boxes,
                float* __restrict__ out) {
    int idx = blockIdx.x * blockDim.x + threadIdx.x;
    const int total = NBOX * CTOT * OH * OW;
    if (idx >= total) return;

    int ow = idx % OW;
    int t = idx / OW;
    int oh = t % OH; t /= OH;
    int c  = t % CTOT;
    int n  = t / CTOT;

    // spatial scales: 304/1216 = 200/800 = 0.25 (shapes fixed by the problem)
    const float sx = 0.25f;
    const float sy = 0.25f;

    float bx1 = __ldg(&boxes[n * 4 + 0]) * sx;
    float by1 = __ldg(&boxes[n * 4 + 1]) * sy;
    float bx2 = __ldg(&boxes[n * 4 + 2]) * sx;
    float by2 = __ldg(&boxes[n * 4 + 3]) * sy;
    float rw = fmaxf(bx2 - bx1, 1.0f);
    float rh = fmaxf(by2 - by1, 1.0f);
    float bw = rw * (1.0f / OW);
    float bh = rh * (1.0f / OH);

    const float* plane;
    if (c < CPL)            plane = feat0 + c * FHW;
    else if (c < 2 * CPL)   plane = g_up1 + (c - CPL) * FHW;
    else                    plane = g_up2 + (c - 2 * CPL) * FHW;

    float acc = 0.0f;
#pragma unroll
    for (int s = 0; s < 4; s++) {
        int syi = s >> 1;
        int sxi = s & 1;
        float Y = by1 + ((float)oh + 0.25f + 0.5f * (float)syi) * bh;
        float X = bx1 + ((float)ow + 0.25f + 0.5f * (float)sxi) * bw;
        bool valid = (Y >= -1.0f) && (Y <= (float)FH) && (X >= -1.0f) && (X <= (float)FW);
        float Yc = fminf(fmaxf(Y, 0.0f), (float)(FH - 1));
        float Xc = fminf(fmaxf(X, 0.0f), (float)(FW - 1));
        int y0 = (int)Yc;
        int x0 = (int)Xc;
        int y1i = min(y0 + 1, FH - 1);
        int x1i = min(x0 + 1, FW - 1);
        float ly = Yc - (float)y0;
        float lx = Xc - (float)x0;
        float hy = 1.0f - ly;
        float hx = 1.0f - lx;
        const float* r0 = plane + y0 * FW;
        const float* r1 = plane + y1i * FW;
        float v = hy * (hx * __ldg(&r0[x0]) + lx * __ldg(&r0[x1i]))
                + ly * (hx * __ldg(&r1[x0]) + lx * __ldg(&r1[x1i]));
        acc += valid ? v : 0.0f;
    }
    out[idx] = acc * 0.25f;
}

extern "C" void kernel_launch(void* const* d_in, const int* in_sizes, int n_in,
                              void* d_out, int out_size) {
    const float* feat0 = (const float*)d_in[0];
    const float* feat1 = (const float*)d_in[1];
    const float* feat2 = (const float*)d_in[2];
    const float* boxes = (const float*)d_in[3];
    float* out = (float*)d_out;

    {
        int total = 2 * CPL * FHW;
        int blocks = (total + 255) / 256;
        upsample_kernel<<<blocks, 256>>>(feat1, feat2);
    }
    {
        int total = NBOX * CTOT * OH * OW;
        int blocks = (total + 255) / 256;
        roialign_kernel<<<blocks, 256>>>(feat0, boxes, out);
    }
}

// round 2
// speedup vs baseline: 1.5881x; 1.5881x over previous
#include <cuda_runtime.h>
#include <cuda_bf16.h>

// Fixed problem shapes
#define NBOX 256
#define CPL  256
#define UH   200      // fused/upsampled map height (level-0 native)
#define UW   304
#define H1   100
#define W1   152
#define H2   50
#define W2   76

// Block: one (box, level). 392 = 8 channel-lanes x 49 cells.
#define TPB 392

__global__ void __launch_bounds__(TPB)
fused_roialign_kernel(const float* __restrict__ feat0,
                      const float* __restrict__ feat1,
                      const float* __restrict__ feat2,
                      const float* __restrict__ boxes,
                      float* __restrict__ out)
{
    const int n   = blockIdx.x;
    const int lvl = blockIdx.y;
    const int tid = threadIdx.x;

    // Level-0 tap tables: [axis][pos][tap]  (axis 0 = x, 1 = y)
    __shared__ float s_w0[2][7][4];
    __shared__ int   s_i0[2][7][4];
    // Coarse-level dense windows
    __shared__ float s_xw[7][8];
    __shared__ int   s_xb[7];
    __shared__ float s_yw[7][6];
    __shared__ int   s_yb[7];

    // ---------------- per-block precompute (taps shared across channels) ----
    if (tid < 14) {
        const int axis = tid / 7;          // 0 = x (ow), 1 = y (oh)
        const int p    = tid % 7;
        // spatial scale 0.25 in both axes (304/1216, 200/800)
        float b1 = boxes[n * 4 + axis]     * 0.25f;
        float b2 = boxes[n * 4 + 2 + axis] * 0.25f;
        float rb = fmaxf(b2 - b1, 1.0f);
        float bt = rb * (1.0f / 7.0f);
        const int updim = axis ? UH : UW;

        if (lvl == 0) {
            #pragma unroll
            for (int s = 0; s < 2; s++) {
                float T  = b1 + ((float)p + 0.25f + 0.5f * (float)s) * bt;
                float Tc = fminf(fmaxf(T, 0.0f), (float)(updim - 1));
                int   i0 = (int)Tc;
                int   i1 = min(i0 + 1, updim - 1);
                float f  = Tc - (float)i0;
                s_i0[axis][p][2 * s + 0] = i0;
                s_i0[axis][p][2 * s + 1] = i1;
                s_w0[axis][p][2 * s + 0] = 0.5f * (1.0f - f);  // 0.5 = per-axis sample avg
                s_w0[axis][p][2 * s + 1] = 0.5f * f;
            }
        } else {
            const float inv  = (lvl == 1) ? 0.5f : 0.25f;
            const int   cdim = axis ? ((lvl == 1) ? H1 : H2)
                                    : ((lvl == 1) ? W1 : W2);
            int   ci[8];
            float cw[8];
            int   mn = 1 << 30;
            int   e  = 0;
            #pragma unroll
            for (int s = 0; s < 2; s++) {
                float T  = b1 + ((float)p + 0.25f + 0.5f * (float)s) * bt;
                float Tc = fminf(fmaxf(T, 0.0f), (float)(updim - 1));
                int   u0 = (int)Tc;
                int   u1 = min(u0 + 1, updim - 1);
                float fu = Tc - (float)u0;
                #pragma unroll
                for (int b = 0; b < 2; b++) {
                    int   u  = b ? u1 : u0;
                    float wu = b ? (0.5f * fu) : (0.5f * (1.0f - fu));
                    // upsample source coord (half-pixel, edge clamp)
                    float g  = ((float)u + 0.5f) * inv - 0.5f;
                    g = fminf(fmaxf(g, 0.0f), (float)(cdim - 1));
                    int   c0 = (int)g;
                    int   c1 = min(c0 + 1, cdim - 1);
                    float fc = g - (float)c0;
                    ci[e] = c0; cw[e] = wu * (1.0f - fc); e++;
                    ci[e] = c1; cw[e] = wu * fc;          e++;
                    mn = min(mn, c0);
                }
            }
            if (axis == 0) {
                int xb = min(mn & ~1, cdim - 8);   // even base, window of 8 in-bounds
                float w[8] = {0, 0, 0, 0, 0, 0, 0, 0};
                #pragma unroll
                for (int k = 0; k < 8; k++) {
                    int off = ci[k] - xb;
                    off = min(max(off, 0), 7);     // defensive (math bounds: 0..7)
                    w[off] += cw[k];
                }
                s_xb[p] = xb;
                #pragma unroll
                for (int k = 0; k < 8; k++) s_xw[p][k] = w[k];
            } else {
                int yb = min(mn, cdim - 6);        // window of 6 rows in-bounds
                float w[6] = {0, 0, 0, 0, 0, 0};
                #pragma unroll
                for (int k = 0; k < 8; k++) {
                    int off = ci[k] - yb;
                    off = min(max(off, 0), 5);     // defensive (math bounds: 0..5)
                    w[off] += cw[k];
                }
                s_yb[p] = yb;
                #pragma unroll
                for (int k = 0; k < 6; k++) s_yw[p][k] = w[k];
            }
        }
    }
    __syncthreads();

    // ---------------- main loop: fixed cell per thread, channel-strided ----
    const int cell = tid % 49;
    const int cl   = tid / 49;                 // 0..7 channel lane
    const int oh   = cell / 7;
    const int ow   = cell % 7;
    float* op = out + ((size_t)(n * 768 + lvl * CPL) * 49) + cell;

    if (lvl == 0) {
        int   xi0 = s_i0[0][ow][0], xi1 = s_i0[0][ow][1], xi2 = s_i0[0][ow][2], xi3 = s_i0[0][ow][3];
        float xw0 = s_w0[0][ow][0], xw1 = s_w0[0][ow][1], xw2 = s_w0[0][ow][2], xw3 = s_w0[0][ow][3];
        int   ro0 = s_i0[1][oh][0] * UW, ro1 = s_i0[1][oh][1] * UW,
              ro2 = s_i0[1][oh][2] * UW, ro3 = s_i0[1][oh][3] * UW;
        float yw0 = s_w0[1][oh][0], yw1 = s_w0[1][oh][1], yw2 = s_w0[1][oh][2], yw3 = s_w0[1][oh][3];

        for (int c = cl; c < CPL; c += 8) {
            const float* pl = feat0 + c * (UH * UW);
            const float* r0 = pl + ro0;
            const float* r1 = pl + ro1;
            const float* r2 = pl + ro2;
            const float* r3 = pl + ro3;
            float s0 = xw0 * __ldg(r0 + xi0) + xw1 * __ldg(r0 + xi1)
                     + xw2 * __ldg(r0 + xi2) + xw3 * __ldg(r0 + xi3);
            float s1 = xw0 * __ldg(r1 + xi0) + xw1 * __ldg(r1 + xi1)
                     + xw2 * __ldg(r1 + xi2) + xw3 * __ldg(r1 + xi3);
            float s2 = xw0 * __ldg(r2 + xi0) + xw1 * __ldg(r2 + xi1)
                     + xw2 * __ldg(r2 + xi2) + xw3 * __ldg(r2 + xi3);
            float s3 = xw0 * __ldg(r3 + xi0) + xw1 * __ldg(r3 + xi1)
                     + xw2 * __ldg(r3 + xi2) + xw3 * __ldg(r3 + xi3);
            float acc = yw0 * s0 + yw1 * s1 + yw2 * s2 + yw3 * s3;
            op[c * 49] = acc;
        }
    } else {
        const float* base = (lvl == 1) ? feat1 : feat2;
        const int cw_  = (lvl == 1) ? W1 : W2;
        const int cstr = (lvl == 1) ? (H1 * W1) : (H2 * W2);
        const int xb = s_xb[ow];
        const int yb = s_yb[oh];
        float xw[8], yw[6];
        #pragma unroll
        for (int k = 0; k < 8; k++) xw[k] = s_xw[ow][k];
        #pragma unroll
        for (int k = 0; k < 6; k++) yw[k] = s_yw[oh][k];

        for (int c = cl; c < CPL; c += 8) {
            const float* pl = base + c * cstr + yb * cw_ + xb;
            float acc = 0.0f;
            #pragma unroll
            for (int r = 0; r < 6; r++) {
                const float2* row = (const float2*)(pl + r * cw_);
                float2 v0 = __ldg(row + 0);
                float2 v1 = __ldg(row + 1);
                float2 v2 = __ldg(row + 2);
                float2 v3 = __ldg(row + 3);
                float rs = xw[0] * v0.x + xw[1] * v0.y
                         + xw[2] * v1.x + xw[3] * v1.y
                         + xw[4] * v2.x + xw[5] * v2.y
                         + xw[6] * v3.x + xw[7] * v3.y;
                acc = fmaf(yw[r], rs, acc);
            }
            op[c * 49] = acc;
        }
    }
}

extern "C" void kernel_launch(void* const* d_in, const int* in_sizes, int n_in,
                              void* d_out, int out_size) {
    const float* feat0 = (const float*)d_in[0];
    const float* feat1 = (const float*)d_in[1];
    const float* feat2 = (const float*)d_in[2];
    const float* boxes = (const float*)d_in[3];
    float* out = (float*)d_out;

    dim3 grid(NBOX, 3);
    fused_roialign_kernel<<<grid, TPB>>>(feat0, feat1, feat2, boxes, out);
}

// round 3
// speedup vs baseline: 2.3244x; 1.4636x over previous
#include <cuda_runtime.h>
#include <cuda_bf16.h>

// Fixed problem shapes
#define NBOX 256
#define CPL  256
#define UH   200
#define UW   304
#define H1   100
#define W1   152
#define H2   50
#define W2   76

#define TPB 392   // 8 channel-lanes x 49 cells

__global__ void __launch_bounds__(TPB)
fused_roialign_kernel(const float* __restrict__ feat0,
                      const float* __restrict__ feat1,
                      const float* __restrict__ feat2,
                      const float* __restrict__ boxes,
                      float* __restrict__ out)
{
    const int n   = blockIdx.x;
    const int lvl = blockIdx.y;
    const int tid = threadIdx.x;

    // Level-0 tap tables: [axis][pos][tap]
    __shared__ float s_w0[2][7][4];
    __shared__ int   s_i0[2][7][4];
    // Coarse-level windows: x = 8 cols (two float4), y = up to 5 rows
    __shared__ float s_xw[7][8];
    __shared__ int   s_xb[7];
    __shared__ float s_yw[7][5];
    __shared__ int   s_yb[7];

    if (tid < 14) {
        const int axis = tid / 7;          // 0 = x, 1 = y
        const int p    = tid % 7;
        float b1 = boxes[n * 4 + axis]     * 0.25f;
        float b2 = boxes[n * 4 + 2 + axis] * 0.25f;
        float rb = fmaxf(b2 - b1, 1.0f);
        float bt = rb * (1.0f / 7.0f);
        const int updim = axis ? UH : UW;

        if (lvl == 0) {
            #pragma unroll
            for (int s = 0; s < 2; s++) {
                float T  = b1 + ((float)p + 0.25f + 0.5f * (float)s) * bt;
                float Tc = fminf(fmaxf(T, 0.0f), (float)(updim - 1));
                int   i0 = (int)Tc;
                int   i1 = min(i0 + 1, updim - 1);
                float f  = Tc - (float)i0;
                s_i0[axis][p][2 * s + 0] = i0;
                s_i0[axis][p][2 * s + 1] = i1;
                s_w0[axis][p][2 * s + 0] = 0.5f * (1.0f - f);
                s_w0[axis][p][2 * s + 1] = 0.5f * f;
            }
        } else {
            const float inv  = (lvl == 1) ? 0.5f : 0.25f;
            const int   cdim = axis ? ((lvl == 1) ? H1 : H2)
                                    : ((lvl == 1) ? W1 : W2);
            const int   R    = (lvl == 1) ? 5 : 4;   // worst-case distinct rows
            int   ci[8];
            float cw[8];
            int   mn = 1 << 30;
            int   e  = 0;
            #pragma unroll
            for (int s = 0; s < 2; s++) {
                float T  = b1 + ((float)p + 0.25f + 0.5f * (float)s) * bt;
                float Tc = fminf(fmaxf(T, 0.0f), (float)(updim - 1));
                int   u0 = (int)Tc;
                int   u1 = min(u0 + 1, updim - 1);
                float fu = Tc - (float)u0;
                #pragma unroll
                for (int b = 0; b < 2; b++) {
                    int   u  = b ? u1 : u0;
                    float wu = b ? (0.5f * fu) : (0.5f * (1.0f - fu));
                    float g  = ((float)u + 0.5f) * inv - 0.5f;
                    g = fminf(fmaxf(g, 0.0f), (float)(cdim - 1));
                    int   c0 = (int)g;
                    int   c1 = min(c0 + 1, cdim - 1);
                    float fc = g - (float)c0;
                    ci[e] = c0; cw[e] = wu * (1.0f - fc); e++;
                    ci[e] = c1; cw[e] = wu * fc;          e++;
                    mn = min(mn, c0);
                }
            }
            if (axis == 0) {
                int xb = min(mn & ~3, cdim - 8);   // float4-aligned, window 8
                float w[8] = {0, 0, 0, 0, 0, 0, 0, 0};
                #pragma unroll
                for (int k = 0; k < 8; k++) {
                    int off = min(max(ci[k] - xb, 0), 7);
                    w[off] += cw[k];
                }
                s_xb[p] = xb;
                #pragma unroll
                for (int k = 0; k < 8; k++) s_xw[p][k] = w[k];
            } else {
                int yb = min(mn, cdim - R);        // R rows, all in-bounds
                float w[5] = {0, 0, 0, 0, 0};
                #pragma unroll
                for (int k = 0; k < 8; k++) {
                    int off = min(max(ci[k] - yb, 0), R - 1);
                    w[off] += cw[k];
                }
                s_yb[p] = yb;
                #pragma unroll
                for (int k = 0; k < 5; k++) s_yw[p][k] = w[k];
            }
        }
    }
    __syncthreads();

    const int cell = tid % 49;
    const int cl   = tid / 49;
    const int oh   = cell / 7;
    const int ow   = cell % 7;
    float* op = out + ((size_t)(n * 768 + lvl * CPL) * 49) + cell;

    if (lvl == 0) {
        int   xi0 = s_i0[0][ow][0], xi1 = s_i0[0][ow][1], xi2 = s_i0[0][ow][2], xi3 = s_i0[0][ow][3];
        float xw0 = s_w0[0][ow][0], xw1 = s_w0[0][ow][1], xw2 = s_w0[0][ow][2], xw3 = s_w0[0][ow][3];
        int   ro0 = s_i0[1][oh][0] * UW, ro1 = s_i0[1][oh][1] * UW,
              ro2 = s_i0[1][oh][2] * UW, ro3 = s_i0[1][oh][3] * UW;
        float yw0 = s_w0[1][oh][0], yw1 = s_w0[1][oh][1], yw2 = s_w0[1][oh][2], yw3 = s_w0[1][oh][3];

        for (int c = cl; c < CPL; c += 8) {
            const float* pl = feat0 + c * (UH * UW);
            const float* r0 = pl + ro0;
            const float* r1 = pl + ro1;
            const float* r2 = pl + ro2;
            const float* r3 = pl + ro3;
            float s0 = xw0 * __ldg(r0 + xi0) + xw1 * __ldg(r0 + xi1)
                     + xw2 * __ldg(r0 + xi2) + xw3 * __ldg(r0 + xi3);
            float s1 = xw0 * __ldg(r1 + xi0) + xw1 * __ldg(r1 + xi1)
                     + xw2 * __ldg(r1 + xi2) + xw3 * __ldg(r1 + xi3);
            float s2 = xw0 * __ldg(r2 + xi0) + xw1 * __ldg(r2 + xi1)
                     + xw2 * __ldg(r2 + xi2) + xw3 * __ldg(r2 + xi3);
            float s3 = xw0 * __ldg(r3 + xi0) + xw1 * __ldg(r3 + xi1)
                     + xw2 * __ldg(r3 + xi2) + xw3 * __ldg(r3 + xi3);
            op[c * 49] = yw0 * s0 + yw1 * s1 + yw2 * s2 + yw3 * s3;
        }
    } else if (lvl == 1) {
        const int xb = s_xb[ow];
        const int yb = s_yb[oh];
        float xw[8], yw[5];
        #pragma unroll
        for (int k = 0; k < 8; k++) xw[k] = s_xw[ow][k];
        #pragma unroll
        for (int k = 0; k < 5; k++) yw[k] = s_yw[oh][k];

        for (int c = cl; c < CPL; c += 8) {
            const float* pl = feat1 + c * (H1 * W1) + yb * W1 + xb;
            float acc = 0.0f;
            #pragma unroll
            for (int r = 0; r < 5; r++) {
                const float4* row = (const float4*)(pl + r * W1);
                float4 a = __ldg(row);
                float4 b = __ldg(row + 1);
                float rs = xw[0] * a.x + xw[1] * a.y + xw[2] * a.z + xw[3] * a.w
                         + xw[4] * b.x + xw[5] * b.y + xw[6] * b.z + xw[7] * b.w;
                acc = fmaf(yw[r], rs, acc);
            }
            op[c * 49] = acc;
        }
    } else {
        const int xb = s_xb[ow];
        const int yb = s_yb[oh];
        float xw[8], yw[4];
        #pragma unroll
        for (int k = 0; k < 8; k++) xw[k] = s_xw[ow][k];
        #pragma unroll
        for (int k = 0; k < 4; k++) yw[k] = s_yw[oh][k];

        for (int c = cl; c < CPL; c += 8) {
            const float* pl = feat2 + c * (H2 * W2) + yb * W2 + xb;
            float acc = 0.0f;
            #pragma unroll
            for (int r = 0; r < 4; r++) {
                const float4* row = (const float4*)(pl + r * W2);
                float4 a = __ldg(row);
                float4 b = __ldg(row + 1);
                float rs = xw[0] * a.x + xw[1] * a.y + xw[2] * a.z + xw[3] * a.w
                         + xw[4] * b.x + xw[5] * b.y + xw[6] * b.z + xw[7] * b.w;
                acc = fmaf(yw[r], rs, acc);
            }
            op[c * 49] = acc;
        }
    }
}

extern "C" void kernel_launch(void* const* d_in, const int* in_sizes, int n_in,
                              void* d_out, int out_size) {
    const float* feat0 = (const float*)d_in[0];
    const float* feat1 = (const float*)d_in[1];
    const float* feat2 = (const float*)d_in[2];
    const float* boxes = (const float*)d_in[3];
    float* out = (float*)d_out;

    dim3 grid(NBOX, 3);
    fused_roialign_kernel<<<grid, TPB>>>(feat0, feat1, feat2, boxes, out);
}